// round 1
// baseline (speedup 1.0000x reference)
#include <cuda_runtime.h>
#include <cuda_bf16.h>
#include <math.h>

#define BSZ 4
#define NV  4096
#define NP1 1024
#define NP2 256
#define KNN 32

// ---------------- scratch (device globals; no allocation allowed) ------------
__device__ int   g_nb1[BSZ*NV*KNN];
__device__ int   g_nb2[BSZ*NP1*KNN];
__device__ int   g_nb3[BSZ*NP2*KNN];
__device__ int   g_nbp[BSZ*NP1*4];
__device__ int   g_near1[BSZ*NV];
__device__ int   g_near2[BSZ*NV];
__device__ float g_fm0[BSZ*NV*128];
__device__ float g_fm1[BSZ*NV*128];
__device__ float g_f  [BSZ*NV*256];        // largest intermediate f (16384x256)
__device__ float g_vp1[BSZ*NP1*3];
__device__ float g_fmp1[BSZ*NP1*128];
__device__ float g_fm2[BSZ*NP1*256];
__device__ float g_fm3[BSZ*NP1*256];
__device__ float g_vp2[BSZ*NP2*3];
__device__ float g_fmp2[BSZ*NP2*256];
__device__ float g_fm4[BSZ*NP2*512];
__device__ float g_fglob[BSZ*512];
__device__ float g_fuse[BSZ*NV*1792];
__device__ float g_h1[BSZ*NV*512];
__device__ float g_h2[BSZ*NV*512];

// ---------------- KNN: brute force, smem-tiled, insertion top-K --------------
// Matches jax: d = |a|^2 + |b|^2 - 2 a.b ; stable ties (earlier index wins),
// self excluded by index. Neighbor ORDER is irrelevant downstream (max-reductions).
template<int K>
__global__ void knn_kernel(const float* __restrict__ verts,
                           const int* __restrict__ qidx, // null => identity
                           int nq, int V, int* __restrict__ out)
{
    int b = blockIdx.y;
    int q = blockIdx.x * 128 + threadIdx.x;
    const float* vb = verts + (size_t)b * V * 3;
    bool active = q < nq;
    int self = -1;
    float qx=0.f, qy=0.f, qz=0.f, qa2=0.f;
    if (active) {
        self = qidx ? qidx[q] : q;
        qx = vb[self*3+0]; qy = vb[self*3+1]; qz = vb[self*3+2];
        qa2 = qx*qx + qy*qy + qz*qz;
    }
    float dk[K]; int ik[K];
#pragma unroll
    for (int i=0;i<K;i++){ dk[i]=3.4e38f; ik[i]=0; }
    float worst = 3.4e38f;

    __shared__ float4 sp[128];
    for (int t0=0; t0<V; t0+=128) {
        int j = t0 + threadIdx.x;   // V is a multiple of 128 always
        float x = vb[j*3+0], y = vb[j*3+1], z = vb[j*3+2];
        sp[threadIdx.x] = make_float4(x,y,z, x*x+y*y+z*z);
        __syncthreads();
        if (active) {
            for (int jj=0; jj<128; jj++) {
                float4 p = sp[jj];
                float d = qa2 + p.w - 2.0f*(qx*p.x + qy*p.y + qz*p.z);
                int gj = t0 + jj;
                if (gj != self && d < worst) {
                    int pos = K-1;
                    while (pos > 0 && dk[pos-1] > d) {
                        dk[pos]=dk[pos-1]; ik[pos]=ik[pos-1]; --pos;
                    }
                    dk[pos]=d; ik[pos]=gj;
                    worst = dk[K-1];
                }
            }
        }
        __syncthreads();
    }
    if (active) {
        int* o = out + ((size_t)b*nq + q)*K;
#pragma unroll
        for (int i=0;i<K;i++) o[i]=ik[i];
    }
}

// ---------------- conv_surface (fm0) ----------------------------------------
__global__ void conv_surface_kernel(const float* __restrict__ verts,
                                    const int* __restrict__ nb,
                                    const float* __restrict__ dir0,
                                    float* __restrict__ fm0)
{
    int bv = blockIdx.x;               // b*NV + v
    int b = bv >> 12, v = bv & (NV-1);
    const float* vb = verts + (size_t)b*NV*3;
    __shared__ float sdx[KNN], sdy[KNN], sdz[KNN];
    int t = threadIdx.x;
    float cx = vb[v*3+0], cy = vb[v*3+1], cz = vb[v*3+2];
    if (t < KNN) {
        int j = nb[(size_t)bv*KNN + t];
        float dx = vb[j*3+0]-cx, dy = vb[j*3+1]-cy, dz = vb[j*3+2]-cz;
        float n = sqrtf(dx*dx+dy*dy+dz*dz);
        float inv = 1.0f / fmaxf(n, 1e-12f);
        sdx[t]=dx*inv; sdy[t]=dy*inv; sdz[t]=dz*inv;
    }
    __syncthreads();
    int k = t;                          // 128 threads = 128 kernels
    float d0 = dir0[k], d1 = dir0[128+k], d2 = dir0[256+k];
    float n = sqrtf(d0*d0+d1*d1+d2*d2);
    float inv = 1.0f / fmaxf(n, 1e-12f);
    d0*=inv; d1*=inv; d2*=inv;
    float m = 0.0f;                     // relu(theta)>=0 so max>=0; relu(max)=max
#pragma unroll
    for (int j=0;j<KNN;j++)
        m = fmaxf(m, sdx[j]*d0 + sdy[j]*d1 + sdz[j]*d2);
    fm0[(size_t)bv*128 + k] = m;
}

// ---------------- conv_layer epilogue: center + max_n(theta * supp_nb) ------
template<int COUT, bool RELU>
__global__ void conv_layer_kernel(const float* __restrict__ verts, int V,
                                  const int* __restrict__ nb,
                                  const float* __restrict__ f,    // (B*V, 2*COUT)
                                  const float* __restrict__ dirs, // (3, COUT)
                                  float* __restrict__ out)        // (B*V, COUT)
{
    int bv = blockIdx.x;
    int b = bv / V, v = bv - b*V;
    const float* vb = verts + (size_t)b*V*3;
    __shared__ float sdx[KNN], sdy[KNN], sdz[KNN];
    __shared__ int   si[KNN];
    int t = threadIdx.x;
    float cx = vb[v*3+0], cy = vb[v*3+1], cz = vb[v*3+2];
    if (t < KNN) {
        int j = nb[(size_t)bv*KNN + t];
        si[t] = j;
        float dx = vb[j*3+0]-cx, dy = vb[j*3+1]-cy, dz = vb[j*3+2]-cz;
        float n = sqrtf(dx*dx+dy*dy+dz*dz);
        float inv = 1.0f / fmaxf(n, 1e-12f);
        sdx[t]=dx*inv; sdy[t]=dy*inv; sdz[t]=dz*inv;
    }
    __syncthreads();
    const float* fb = f + (size_t)b*V*(2*COUT);
    for (int co = t; co < COUT; co += blockDim.x) {
        float d0 = dirs[co], d1 = dirs[COUT+co], d2 = dirs[2*COUT+co];
        float n = sqrtf(d0*d0+d1*d1+d2*d2);
        float inv = 1.0f / fmaxf(n, 1e-12f);
        d0*=inv; d1*=inv; d2*=inv;
        float m = -3.4e38f;
#pragma unroll 8
        for (int j=0;j<KNN;j++) {
            float th = fmaxf(sdx[j]*d0 + sdy[j]*d1 + sdz[j]*d2, 0.0f);
            float val = th * fb[(size_t)si[j]*(2*COUT) + COUT + co];
            m = fmaxf(m, val);
        }
        float r = fb[(size_t)v*(2*COUT) + co] + m;
        out[((size_t)b*V+v)*COUT + co] = RELU ? fmaxf(r, 0.0f) : r;
    }
}

// ---------------- pool: gather sampled verts + max over 4 NN ----------------
__global__ void pool_kernel(const float* __restrict__ verts,
                            const float* __restrict__ fm,
                            int V, int C,
                            const int* __restrict__ sidx,
                            const int* __restrict__ nb4, int ns,
                            float* __restrict__ vout, float* __restrict__ fout)
{
    int bq = blockIdx.x;
    int b = bq / ns, q = bq - b*ns;
    int t = threadIdx.x;
    int sv = sidx[q];
    if (t < 3) vout[(size_t)bq*3 + t] = verts[((size_t)b*V + sv)*3 + t];
    const int* nbq = nb4 + (size_t)bq*4;
    int j0=nbq[0], j1=nbq[1], j2=nbq[2], j3=nbq[3];
    const float* fb = fm + (size_t)b*V*C;
    for (int c=t; c<C; c+=blockDim.x) {
        float m = fmaxf(fmaxf(fb[(size_t)j0*C+c], fb[(size_t)j1*C+c]),
                        fmaxf(fb[(size_t)j2*C+c], fb[(size_t)j3*C+c]));
        fout[(size_t)bq*C + c] = m;
    }
}

// ---------------- nearest: argmin over source set (first-min wins) ----------
__global__ void nearest_kernel(const float* __restrict__ verts,
                               const float* __restrict__ src,
                               int V, int S, int* __restrict__ out)
{
    int b = blockIdx.y;
    int q = blockIdx.x * 128 + threadIdx.x;
    const float* vb = verts + (size_t)b*V*3;
    const float* sb = src + (size_t)b*S*3;
    float qx = vb[q*3+0], qy = vb[q*3+1], qz = vb[q*3+2];
    float qa2 = qx*qx + qy*qy + qz*qz;
    float best = 3.4e38f; int bi = 0;
    __shared__ float4 sp[128];
    for (int t0=0; t0<S; t0+=128) {
        int j = t0 + threadIdx.x;      // S in {1024,256}: multiple of 128
        float x = sb[j*3+0], y = sb[j*3+1], z = sb[j*3+2];
        sp[threadIdx.x] = make_float4(x,y,z, x*x+y*y+z*z);
        __syncthreads();
        for (int jj=0; jj<128; jj++) {
            float4 p = sp[jj];
            float d = qa2 + p.w - 2.0f*(qx*p.x + qy*p.y + qz*p.z);
            if (d < best) { best = d; bi = t0+jj; }
        }
        __syncthreads();
    }
    out[(size_t)b*V + q] = bi;
}

// ---------------- global feature: max over NP2 verts ------------------------
__global__ void fglobal_kernel(const float* __restrict__ fm4, float* __restrict__ g)
{
    int b = blockIdx.x, c = threadIdx.x;   // 512 threads
    float m = -3.4e38f;
    for (int v=0; v<NP2; v++) m = fmaxf(m, fm4[((size_t)b*NP2+v)*512 + c]);
    g[(size_t)b*512 + c] = m;
}

// ---------------- fuse assembly ----------------------------------------------
__global__ void fuse_kernel(const float* __restrict__ fm0, const float* __restrict__ fm1,
                            const float* __restrict__ fm2, const float* __restrict__ fm3,
                            const float* __restrict__ fm4, const float* __restrict__ fg,
                            const int* __restrict__ near1, const int* __restrict__ near2,
                            float* __restrict__ fuse)
{
    int bv = blockIdx.x;
    int b = bv >> 12;
    int n1 = near1[bv], n2 = near2[bv];
    float* o = fuse + (size_t)bv*1792;
    for (int c = threadIdx.x; c < 1792; c += blockDim.x) {
        float val;
        if (c < 128)        val = fm0[(size_t)bv*128 + c];
        else if (c < 256)   val = fm1[(size_t)bv*128 + (c-128)];
        else if (c < 512)   val = fm2[((size_t)b*NP1+n1)*256 + (c-256)];
        else if (c < 768)   val = fm3[((size_t)b*NP1+n1)*256 + (c-512)];
        else if (c < 1280)  val = fm4[((size_t)b*NP2+n2)*512 + (c-768)];
        else                val = fg [(size_t)b*512 + (c-1280)];
        o[c] = val;
    }
}

// ---------------- SGEMM: C(MxN) = A(MxK) @ B + bias, optional relu ----------
// BT=false: B is (K,N) row-major.  BT=true: B is (N,K) row-major (i.e. B^T).
// 64x64 tile, 16-deep K tiles, 256 threads, 4x4 register micro-tile.
template<bool BT, bool RELU>
__global__ void gemm_kernel(const float* __restrict__ A, const float* __restrict__ B,
                            const float* __restrict__ bias, float* __restrict__ C,
                            int M, int N, int K)
{
    __shared__ float As[16][65];
    __shared__ float Bs[16][68];
    int tid = threadIdx.x;
    int tx = tid & 15, ty = tid >> 4;
    int m0 = blockIdx.y * 64, n0 = blockIdx.x * 64;

    float acc[4][4] = {};
    for (int k0 = 0; k0 < K; k0 += 16) {
#pragma unroll
        for (int l=0; l<4; l++) {                 // A tile: 64m x 16k
            int idx = tid + l*256;
            int m = idx >> 4, kk = idx & 15;
            int gm = m0 + m, gk = k0 + kk;
            As[kk][m] = (gm < M && gk < K) ? A[(size_t)gm*K + gk] : 0.0f;
        }
#pragma unroll
        for (int l=0; l<4; l++) {                 // B tile: 16k x 64n
            int idx = tid + l*256;
            float v = 0.0f;
            if (BT) {
                int kk = idx & 15, n = idx >> 4;
                int gk = k0 + kk, gn = n0 + n;
                if (gk < K && gn < N) v = B[(size_t)gn*K + gk];
                Bs[kk][n] = v;
            } else {
                int kk = idx >> 6, n = idx & 63;
                int gk = k0 + kk, gn = n0 + n;
                if (gk < K && gn < N) v = B[(size_t)gk*N + gn];
                Bs[kk][n] = v;
            }
        }
        __syncthreads();
#pragma unroll
        for (int kk=0; kk<16; kk++) {
            float a[4], bb[4];
#pragma unroll
            for (int i=0;i<4;i++) a[i] = As[kk][ty*4+i];
#pragma unroll
            for (int j=0;j<4;j++) bb[j] = Bs[kk][tx*4+j];
#pragma unroll
            for (int i=0;i<4;i++)
#pragma unroll
                for (int j=0;j<4;j++)
                    acc[i][j] += a[i]*bb[j];
        }
        __syncthreads();
    }
#pragma unroll
    for (int i=0;i<4;i++) {
        int gm = m0 + ty*4 + i;
        if (gm >= M) continue;
#pragma unroll
        for (int j=0;j<4;j++) {
            int gn = n0 + tx*4 + j;
            if (gn >= N) continue;
            float v = acc[i][j] + bias[gn];
            if (RELU) v = fmaxf(v, 0.0f);
            C[(size_t)gm*N + gn] = v;
        }
    }
}

// -----------------------------------------------------------------------------
static void* sym_addr(const void* symbol) {
    void* p = nullptr;
    cudaGetSymbolAddress(&p, symbol);
    return p;
}

extern "C" void kernel_launch(void* const* d_in, const int* in_sizes, int n_in,
                              void* d_out, int out_size)
{
    (void)in_sizes; (void)n_in; (void)out_size;
    const float* vertices = (const float*)d_in[0];
    const int*   sidx1    = (const int*)  d_in[1];
    const int*   sidx2    = (const int*)  d_in[2];
    const float* dir0     = (const float*)d_in[3];
    const float* w1 = (const float*)d_in[4];  const float* b1 = (const float*)d_in[5];  const float* d1 = (const float*)d_in[6];
    const float* w2 = (const float*)d_in[7];  const float* b2 = (const float*)d_in[8];  const float* d2 = (const float*)d_in[9];
    const float* w3 = (const float*)d_in[10]; const float* b3 = (const float*)d_in[11]; const float* d3 = (const float*)d_in[12];
    const float* w4 = (const float*)d_in[13]; const float* b4 = (const float*)d_in[14]; const float* d4 = (const float*)d_in[15];
    const float* cw1 = (const float*)d_in[16]; const float* cb1 = (const float*)d_in[17];
    const float* cw2 = (const float*)d_in[18]; const float* cb2 = (const float*)d_in[19];
    const float* cw3 = (const float*)d_in[20]; const float* cb3 = (const float*)d_in[21];
    float* out = (float*)d_out;

    int*   nb1   = (int*)  sym_addr(g_nb1);
    int*   nb2   = (int*)  sym_addr(g_nb2);
    int*   nb3   = (int*)  sym_addr(g_nb3);
    int*   nbp   = (int*)  sym_addr(g_nbp);
    int*   near1 = (int*)  sym_addr(g_near1);
    int*   near2 = (int*)  sym_addr(g_near2);
    float* fm0   = (float*)sym_addr(g_fm0);
    float* fm1   = (float*)sym_addr(g_fm1);
    float* fbuf  = (float*)sym_addr(g_f);
    float* vp1   = (float*)sym_addr(g_vp1);
    float* fmp1  = (float*)sym_addr(g_fmp1);
    float* fm2   = (float*)sym_addr(g_fm2);
    float* fm3   = (float*)sym_addr(g_fm3);
    float* vp2   = (float*)sym_addr(g_vp2);
    float* fmp2  = (float*)sym_addr(g_fmp2);
    float* fm4   = (float*)sym_addr(g_fm4);
    float* fglob = (float*)sym_addr(g_fglob);
    float* fuse  = (float*)sym_addr(g_fuse);
    float* h1    = (float*)sym_addr(g_h1);
    float* h2    = (float*)sym_addr(g_h2);

    // 1. full-res KNN(32)
    knn_kernel<KNN><<<dim3(NV/128, BSZ), 128>>>(vertices, nullptr, NV, NV, nb1);
    // 2. fm0 = conv_surface
    conv_surface_kernel<<<BSZ*NV, 128>>>(vertices, nb1, dir0, fm0);
    // 3-4. fm1 = relu(conv_layer(fm0; w1,b1,d1; 128))
    gemm_kernel<false,false><<<dim3(256/64, (BSZ*NV)/64), 256>>>(fm0, w1, b1, fbuf, BSZ*NV, 256, 128);
    conv_layer_kernel<128,true><<<BSZ*NV, 128>>>(vertices, NV, nb1, fbuf, d1, fm1);
    // 5-6. pool1
    knn_kernel<4><<<dim3(NP1/128, BSZ), 128>>>(vertices, sidx1, NP1, NV, nbp);
    pool_kernel<<<BSZ*NP1, 128>>>(vertices, fm1, NV, 128, sidx1, nbp, NP1, vp1, fmp1);
    // 7. KNN(32) on pooled level 1
    knn_kernel<KNN><<<dim3(NP1/128, BSZ), 128>>>(vp1, nullptr, NP1, NP1, nb2);
    // 8-9. fm2 = relu(conv_layer(fmp1; w2,b2,d2; 256))
    gemm_kernel<false,false><<<dim3(512/64, (BSZ*NP1)/64), 256>>>(fmp1, w2, b2, fbuf, BSZ*NP1, 512, 128);
    conv_layer_kernel<256,true><<<BSZ*NP1, 256>>>(vp1, NP1, nb2, fbuf, d2, fm2);
    // 10-11. fm3 = relu(conv_layer(fm2; w3,b3,d3; 256))
    gemm_kernel<false,false><<<dim3(512/64, (BSZ*NP1)/64), 256>>>(fm2, w3, b3, fbuf, BSZ*NP1, 512, 256);
    conv_layer_kernel<256,true><<<BSZ*NP1, 256>>>(vp1, NP1, nb2, fbuf, d3, fm3);
    // 12-13. pool2
    knn_kernel<4><<<dim3(NP2/128, BSZ), 128>>>(vp1, sidx2, NP2, NP1, nbp);
    pool_kernel<<<BSZ*NP2, 256>>>(vp1, fm3, NP1, 256, sidx2, nbp, NP2, vp2, fmp2);
    // 14. KNN(32) on pooled level 2
    knn_kernel<KNN><<<dim3(NP2/128, BSZ), 128>>>(vp2, nullptr, NP2, NP2, nb3);
    // 15-16. fm4 = conv_layer(fmp2; w4,b4,d4; 512)  (no relu)
    gemm_kernel<false,false><<<dim3(1024/64, (BSZ*NP2)/64), 256>>>(fmp2, w4, b4, fbuf, BSZ*NP2, 1024, 256);
    conv_layer_kernel<512,false><<<BSZ*NP2, 256>>>(vp2, NP2, nb3, fbuf, d4, fm4);
    // 17. global max feature
    fglobal_kernel<<<BSZ, 512>>>(fm4, fglob);
    // 18. nearest-neighbor upsample indices
    nearest_kernel<<<dim3(NV/128, BSZ), 128>>>(vertices, vp1, NV, NP1, near1);
    nearest_kernel<<<dim3(NV/128, BSZ), 128>>>(vertices, vp2, NV, NP2, near2);
    // 19. fuse (16384 x 1792)
    fuse_kernel<<<BSZ*NV, 256>>>(fm0, fm1, fm2, fm3, fm4, fglob, near1, near2, fuse);
    // 20-22. MLP head
    gemm_kernel<true,true ><<<dim3(512/64, (BSZ*NV)/64), 256>>>(fuse, cw1, cb1, h1, BSZ*NV, 512, 1792);
    gemm_kernel<true,true ><<<dim3(512/64, (BSZ*NV)/64), 256>>>(h1,   cw2, cb2, h2, BSZ*NV, 512, 512);
    gemm_kernel<true,false><<<dim3(1,       (BSZ*NV)/64), 256>>>(h2,  cw3, cb3, out, BSZ*NV, 13, 512);
}

// round 2
// speedup vs baseline: 1.2658x; 1.2658x over previous
#include <cuda_runtime.h>
#include <cuda_bf16.h>
#include <math.h>

#define BSZ 4
#define NV  4096
#define NP1 1024
#define NP2 256
#define KNN 32

// ---------------- scratch (device globals; no allocation allowed) ------------
__device__ int   g_nb1[BSZ*NV*KNN];
__device__ int   g_nb2[BSZ*NP1*KNN];
__device__ int   g_nb3[BSZ*NP2*KNN];
__device__ int   g_nbp[BSZ*NP1*4];
__device__ int   g_near1[BSZ*NV];
__device__ int   g_near2[BSZ*NV];
__device__ float g_fm0[BSZ*NV*128];
__device__ float g_fm1[BSZ*NV*128];
__device__ float g_f  [BSZ*NV*256];        // largest intermediate f (16384x256)
__device__ float g_vp1[BSZ*NP1*3];
__device__ float g_fmp1[BSZ*NP1*128];
__device__ float g_fm2[BSZ*NP1*256];
__device__ float g_fm3[BSZ*NP1*256];
__device__ float g_vp2[BSZ*NP2*3];
__device__ float g_fmp2[BSZ*NP2*256];
__device__ float g_fm4[BSZ*NP2*512];
__device__ float g_fglob[BSZ*512];
__device__ float g_fuse[BSZ*NV*1792];
__device__ float g_h1[BSZ*NV*512];
__device__ float g_h2[BSZ*NV*512];

// ---------------- KNN: brute force, smem-tiled, insertion top-K --------------
template<int K>
__global__ void knn_kernel(const float* __restrict__ verts,
                           const int* __restrict__ qidx, // null => identity
                           int nq, int V, int* __restrict__ out)
{
    int b = blockIdx.y;
    int q = blockIdx.x * 128 + threadIdx.x;
    const float* vb = verts + (size_t)b * V * 3;
    bool active = q < nq;
    int self = -1;
    float qx=0.f, qy=0.f, qz=0.f, qa2=0.f;
    if (active) {
        self = qidx ? qidx[q] : q;
        qx = vb[self*3+0]; qy = vb[self*3+1]; qz = vb[self*3+2];
        qa2 = qx*qx + qy*qy + qz*qz;
    }
    float dk[K]; int ik[K];
#pragma unroll
    for (int i=0;i<K;i++){ dk[i]=3.4e38f; ik[i]=0; }
    float worst = 3.4e38f;

    __shared__ float4 sp[128];
    for (int t0=0; t0<V; t0+=128) {
        int j = t0 + threadIdx.x;   // V is a multiple of 128 always
        float x = vb[j*3+0], y = vb[j*3+1], z = vb[j*3+2];
        sp[threadIdx.x] = make_float4(x,y,z, x*x+y*y+z*z);
        __syncthreads();
        if (active) {
            for (int jj=0; jj<128; jj++) {
                float4 p = sp[jj];
                float d = qa2 + p.w - 2.0f*(qx*p.x + qy*p.y + qz*p.z);
                int gj = t0 + jj;
                if (gj != self && d < worst) {
                    int pos = K-1;
                    while (pos > 0 && dk[pos-1] > d) {
                        dk[pos]=dk[pos-1]; ik[pos]=ik[pos-1]; --pos;
                    }
                    dk[pos]=d; ik[pos]=gj;
                    worst = dk[K-1];
                }
            }
        }
        __syncthreads();
    }
    if (active) {
        int* o = out + ((size_t)b*nq + q)*K;
#pragma unroll
        for (int i=0;i<K;i++) o[i]=ik[i];
    }
}

// ---------------- conv_surface (fm0) ----------------------------------------
__global__ void conv_surface_kernel(const float* __restrict__ verts,
                                    const int* __restrict__ nb,
                                    const float* __restrict__ dir0,
                                    float* __restrict__ fm0)
{
    int bv = blockIdx.x;               // b*NV + v
    int b = bv >> 12, v = bv & (NV-1);
    const float* vb = verts + (size_t)b*NV*3;
    __shared__ float sdx[KNN], sdy[KNN], sdz[KNN];
    int t = threadIdx.x;
    float cx = vb[v*3+0], cy = vb[v*3+1], cz = vb[v*3+2];
    if (t < KNN) {
        int j = nb[(size_t)bv*KNN + t];
        float dx = vb[j*3+0]-cx, dy = vb[j*3+1]-cy, dz = vb[j*3+2]-cz;
        float n = sqrtf(dx*dx+dy*dy+dz*dz);
        float inv = 1.0f / fmaxf(n, 1e-12f);
        sdx[t]=dx*inv; sdy[t]=dy*inv; sdz[t]=dz*inv;
    }
    __syncthreads();
    int k = t;                          // 128 threads = 128 kernels
    float d0 = dir0[k], d1 = dir0[128+k], d2 = dir0[256+k];
    float n = sqrtf(d0*d0+d1*d1+d2*d2);
    float inv = 1.0f / fmaxf(n, 1e-12f);
    d0*=inv; d1*=inv; d2*=inv;
    float m = 0.0f;
#pragma unroll
    for (int j=0;j<KNN;j++)
        m = fmaxf(m, sdx[j]*d0 + sdy[j]*d1 + sdz[j]*d2);
    fm0[(size_t)bv*128 + k] = m;
}

// ---------------- conv_layer epilogue: center + max_n(theta * supp_nb) ------
template<int COUT, bool RELU>
__global__ void conv_layer_kernel(const float* __restrict__ verts, int V,
                                  const int* __restrict__ nb,
                                  const float* __restrict__ f,    // (B*V, 2*COUT)
                                  const float* __restrict__ dirs, // (3, COUT)
                                  float* __restrict__ out)        // (B*V, COUT)
{
    int bv = blockIdx.x;
    int b = bv / V, v = bv - b*V;
    const float* vb = verts + (size_t)b*V*3;
    __shared__ float sdx[KNN], sdy[KNN], sdz[KNN];
    __shared__ int   si[KNN];
    int t = threadIdx.x;
    float cx = vb[v*3+0], cy = vb[v*3+1], cz = vb[v*3+2];
    if (t < KNN) {
        int j = nb[(size_t)bv*KNN + t];
        si[t] = j;
        float dx = vb[j*3+0]-cx, dy = vb[j*3+1]-cy, dz = vb[j*3+2]-cz;
        float n = sqrtf(dx*dx+dy*dy+dz*dz);
        float inv = 1.0f / fmaxf(n, 1e-12f);
        sdx[t]=dx*inv; sdy[t]=dy*inv; sdz[t]=dz*inv;
    }
    __syncthreads();
    const float* fb = f + (size_t)b*V*(2*COUT);
    for (int co = t; co < COUT; co += blockDim.x) {
        float d0 = dirs[co], d1 = dirs[COUT+co], d2 = dirs[2*COUT+co];
        float n = sqrtf(d0*d0+d1*d1+d2*d2);
        float inv = 1.0f / fmaxf(n, 1e-12f);
        d0*=inv; d1*=inv; d2*=inv;
        float m = -3.4e38f;
#pragma unroll 8
        for (int j=0;j<KNN;j++) {
            float th = fmaxf(sdx[j]*d0 + sdy[j]*d1 + sdz[j]*d2, 0.0f);
            float val = th * fb[(size_t)si[j]*(2*COUT) + COUT + co];
            m = fmaxf(m, val);
        }
        float r = fb[(size_t)v*(2*COUT) + co] + m;
        out[((size_t)b*V+v)*COUT + co] = RELU ? fmaxf(r, 0.0f) : r;
    }
}

// ---------------- pool: gather sampled verts + max over 4 NN ----------------
__global__ void pool_kernel(const float* __restrict__ verts,
                            const float* __restrict__ fm,
                            int V, int C,
                            const int* __restrict__ sidx,
                            const int* __restrict__ nb4, int ns,
                            float* __restrict__ vout, float* __restrict__ fout)
{
    int bq = blockIdx.x;
    int b = bq / ns, q = bq - b*ns;
    int t = threadIdx.x;
    int sv = sidx[q];
    if (t < 3) vout[(size_t)bq*3 + t] = verts[((size_t)b*V + sv)*3 + t];
    const int* nbq = nb4 + (size_t)bq*4;
    int j0=nbq[0], j1=nbq[1], j2=nbq[2], j3=nbq[3];
    const float* fb = fm + (size_t)b*V*C;
    for (int c=t; c<C; c+=blockDim.x) {
        float m = fmaxf(fmaxf(fb[(size_t)j0*C+c], fb[(size_t)j1*C+c]),
                        fmaxf(fb[(size_t)j2*C+c], fb[(size_t)j3*C+c]));
        fout[(size_t)bq*C + c] = m;
    }
}

// ---------------- nearest: argmin over source set (first-min wins) ----------
__global__ void nearest_kernel(const float* __restrict__ verts,
                               const float* __restrict__ src,
                               int V, int S, int* __restrict__ out)
{
    int b = blockIdx.y;
    int q = blockIdx.x * 128 + threadIdx.x;
    const float* vb = verts + (size_t)b*V*3;
    const float* sb = src + (size_t)b*S*3;
    float qx = vb[q*3+0], qy = vb[q*3+1], qz = vb[q*3+2];
    float qa2 = qx*qx + qy*qy + qz*qz;
    float best = 3.4e38f; int bi = 0;
    __shared__ float4 sp[128];
    for (int t0=0; t0<S; t0+=128) {
        int j = t0 + threadIdx.x;
        float x = sb[j*3+0], y = sb[j*3+1], z = sb[j*3+2];
        sp[threadIdx.x] = make_float4(x,y,z, x*x+y*y+z*z);
        __syncthreads();
        for (int jj=0; jj<128; jj++) {
            float4 p = sp[jj];
            float d = qa2 + p.w - 2.0f*(qx*p.x + qy*p.y + qz*p.z);
            if (d < best) { best = d; bi = t0+jj; }
        }
        __syncthreads();
    }
    out[(size_t)b*V + q] = bi;
}

// ---------------- global feature: max over NP2 verts ------------------------
__global__ void fglobal_kernel(const float* __restrict__ fm4, float* __restrict__ g)
{
    int b = blockIdx.x, c = threadIdx.x;   // 512 threads
    float m = -3.4e38f;
    for (int v=0; v<NP2; v++) m = fmaxf(m, fm4[((size_t)b*NP2+v)*512 + c]);
    g[(size_t)b*512 + c] = m;
}

// ---------------- fuse assembly ----------------------------------------------
__global__ void fuse_kernel(const float* __restrict__ fm0, const float* __restrict__ fm1,
                            const float* __restrict__ fm2, const float* __restrict__ fm3,
                            const float* __restrict__ fm4, const float* __restrict__ fg,
                            const int* __restrict__ near1, const int* __restrict__ near2,
                            float* __restrict__ fuse)
{
    int bv = blockIdx.x;
    int b = bv >> 12;
    int n1 = near1[bv], n2 = near2[bv];
    float* o = fuse + (size_t)bv*1792;
    for (int c = threadIdx.x; c < 1792; c += blockDim.x) {
        float val;
        if (c < 128)        val = fm0[(size_t)bv*128 + c];
        else if (c < 256)   val = fm1[(size_t)bv*128 + (c-128)];
        else if (c < 512)   val = fm2[((size_t)b*NP1+n1)*256 + (c-256)];
        else if (c < 768)   val = fm3[((size_t)b*NP1+n1)*256 + (c-512)];
        else if (c < 1280)  val = fm4[((size_t)b*NP2+n2)*512 + (c-768)];
        else                val = fg [(size_t)b*512 + (c-1280)];
        o[c] = val;
    }
}

// ---------------- SGEMM 128x128x8, 8x8 micro-tile, double-buffered ----------
// REQUIREMENTS (guaranteed by call sites): M%128==0, N%128==0, K%8==0,
// A/B/C 16B-aligned.  BT=false: B is (K,N) row-major.  BT=true: B is (N,K).
#define SMS 132   // smem row stride (floats): 16B-aligned (528B), kills xpose conflicts
template<bool BT, bool RELU>
__global__ __launch_bounds__(256, 2)
void gemm128(const float* __restrict__ A, const float* __restrict__ B,
             const float* __restrict__ bias, float* __restrict__ C,
             int M, int N, int K)
{
    __shared__ __align__(16) float As[2][8*SMS];
    __shared__ __align__(16) float Bs[2][8*SMS];
    const int tid = threadIdx.x;
    const int tx = tid & 15;        // n-direction
    const int ty = tid >> 4;        // m-direction
    const int m0 = blockIdx.y * 128;
    const int n0 = blockIdx.x * 128;

    // A global load: thread -> (row = tid>>1, kpart = (tid&1)*4), one float4
    const int arow = tid >> 1;
    const int akp  = (tid & 1) * 4;
    const float* Aptr = A + (size_t)(m0 + arow) * K + akp;

    // B global load
    const float* Bptr;
    int bkk = 0, bn4 = 0;
    if (BT) {
        Bptr = B + (size_t)(n0 + arow) * K + akp;   // same decomposition as A
    } else {
        bkk = tid >> 5; bn4 = (tid & 31) * 4;
        Bptr = B + (size_t)bkk * N + n0 + bn4;
    }

    float acc[8][8];
#pragma unroll
    for (int i=0;i<8;i++)
#pragma unroll
        for (int j=0;j<8;j++) acc[i][j]=0.f;

    const int NT = K >> 3;

    // prologue: tile 0
    float4 areg = *(const float4*)Aptr;
    float4 breg = *(const float4*)Bptr;
    As[0][(akp+0)*SMS+arow]=areg.x;
    As[0][(akp+1)*SMS+arow]=areg.y;
    As[0][(akp+2)*SMS+arow]=areg.z;
    As[0][(akp+3)*SMS+arow]=areg.w;
    if (BT) {
        Bs[0][(akp+0)*SMS+arow]=breg.x;
        Bs[0][(akp+1)*SMS+arow]=breg.y;
        Bs[0][(akp+2)*SMS+arow]=breg.z;
        Bs[0][(akp+3)*SMS+arow]=breg.w;
    } else {
        *(float4*)&Bs[0][bkk*SMS+bn4] = breg;
    }
    __syncthreads();

    for (int kt=0; kt<NT; kt++) {
        const int cur = kt & 1;
        if (kt+1 < NT) {
            areg = *(const float4*)(Aptr + (size_t)(kt+1)*8);
            if (BT) breg = *(const float4*)(Bptr + (size_t)(kt+1)*8);
            else    breg = *(const float4*)(Bptr + (size_t)(kt+1)*8*N);
        }
        const float* as = As[cur];
        const float* bs = Bs[cur];
#pragma unroll
        for (int kk=0; kk<8; kk++) {
            float4 a0 = *(const float4*)&as[kk*SMS + ty*4];
            float4 a1 = *(const float4*)&as[kk*SMS + 64 + ty*4];
            float4 b0 = *(const float4*)&bs[kk*SMS + tx*4];
            float4 b1 = *(const float4*)&bs[kk*SMS + 64 + tx*4];
            float av[8] = {a0.x,a0.y,a0.z,a0.w,a1.x,a1.y,a1.z,a1.w};
            float bv[8] = {b0.x,b0.y,b0.z,b0.w,b1.x,b1.y,b1.z,b1.w};
#pragma unroll
            for (int i=0;i<8;i++)
#pragma unroll
                for (int j=0;j<8;j++)
                    acc[i][j] += av[i]*bv[j];
        }
        if (kt+1 < NT) {
            const int nxt = cur ^ 1;
            As[nxt][(akp+0)*SMS+arow]=areg.x;
            As[nxt][(akp+1)*SMS+arow]=areg.y;
            As[nxt][(akp+2)*SMS+arow]=areg.z;
            As[nxt][(akp+3)*SMS+arow]=areg.w;
            if (BT) {
                Bs[nxt][(akp+0)*SMS+arow]=breg.x;
                Bs[nxt][(akp+1)*SMS+arow]=breg.y;
                Bs[nxt][(akp+2)*SMS+arow]=breg.z;
                Bs[nxt][(akp+3)*SMS+arow]=breg.w;
            } else {
                *(float4*)&Bs[nxt][bkk*SMS+bn4] = breg;
            }
        }
        __syncthreads();
    }

    // epilogue: bias (+relu), float4 stores
#pragma unroll
    for (int ih=0; ih<2; ih++)
#pragma unroll
    for (int ii=0; ii<4; ii++) {
        const int i = ih*4 + ii;
        const int gm = m0 + ih*64 + ty*4 + ii;
        float* crow = C + (size_t)gm*N + n0;
#pragma unroll
        for (int jh=0; jh<2; jh++) {
            const int cb = jh*64 + tx*4;
            float4 bv = *(const float4*)&bias[n0 + cb];
            float4 v;
            v.x = acc[i][jh*4+0] + bv.x;
            v.y = acc[i][jh*4+1] + bv.y;
            v.z = acc[i][jh*4+2] + bv.z;
            v.w = acc[i][jh*4+3] + bv.w;
            if (RELU) {
                v.x = fmaxf(v.x, 0.f); v.y = fmaxf(v.y, 0.f);
                v.z = fmaxf(v.z, 0.f); v.w = fmaxf(v.w, 0.f);
            }
            *(float4*)&crow[cb] = v;
        }
    }
}

// ---------------- head: out(16 rows x 13) = h2 @ cw3^T + cb3 ----------------
__global__ void head_kernel(const float* __restrict__ h2,
                            const float* __restrict__ cw3,
                            const float* __restrict__ cb3,
                            float* __restrict__ out)
{
    __shared__ float sh[16][512];
    __shared__ float sw[13*513];
    const int tid = threadIdx.x;            // 256 threads
    const int r = tid >> 4, c = tid & 15;
    const int row0 = blockIdx.x * 16;
    for (int i = tid; i < 16*512; i += 256)
        sh[i>>9][i&511] = h2[(size_t)row0*512 + i];
    for (int i = tid; i < 13*512; i += 256)
        sw[(i>>9)*513 + (i&511)] = cw3[i];
    __syncthreads();
    if (c < 13) {
        float acc = cb3[c];
        const float* w = &sw[c*513];
        const float* hrow = sh[r];
#pragma unroll 8
        for (int k=0;k<512;k++) acc += hrow[k]*w[k];
        out[(size_t)(row0+r)*13 + c] = acc;
    }
}

// -----------------------------------------------------------------------------
static void* sym_addr(const void* symbol) {
    void* p = nullptr;
    cudaGetSymbolAddress(&p, symbol);
    return p;
}

extern "C" void kernel_launch(void* const* d_in, const int* in_sizes, int n_in,
                              void* d_out, int out_size)
{
    (void)in_sizes; (void)n_in; (void)out_size;
    const float* vertices = (const float*)d_in[0];
    const int*   sidx1    = (const int*)  d_in[1];
    const int*   sidx2    = (const int*)  d_in[2];
    const float* dir0     = (const float*)d_in[3];
    const float* w1 = (const float*)d_in[4];  const float* b1 = (const float*)d_in[5];  const float* d1 = (const float*)d_in[6];
    const float* w2 = (const float*)d_in[7];  const float* b2 = (const float*)d_in[8];  const float* d2 = (const float*)d_in[9];
    const float* w3 = (const float*)d_in[10]; const float* b3 = (const float*)d_in[11]; const float* d3 = (const float*)d_in[12];
    const float* w4 = (const float*)d_in[13]; const float* b4 = (const float*)d_in[14]; const float* d4 = (const float*)d_in[15];
    const float* cw1 = (const float*)d_in[16]; const float* cb1 = (const float*)d_in[17];
    const float* cw2 = (const float*)d_in[18]; const float* cb2 = (const float*)d_in[19];
    const float* cw3 = (const float*)d_in[20]; const float* cb3 = (const float*)d_in[21];
    float* out = (float*)d_out;

    int*   nb1   = (int*)  sym_addr(g_nb1);
    int*   nb2   = (int*)  sym_addr(g_nb2);
    int*   nb3   = (int*)  sym_addr(g_nb3);
    int*   nbp   = (int*)  sym_addr(g_nbp);
    int*   near1 = (int*)  sym_addr(g_near1);
    int*   near2 = (int*)  sym_addr(g_near2);
    float* fm0   = (float*)sym_addr(g_fm0);
    float* fm1   = (float*)sym_addr(g_fm1);
    float* fbuf  = (float*)sym_addr(g_f);
    float* vp1   = (float*)sym_addr(g_vp1);
    float* fmp1  = (float*)sym_addr(g_fmp1);
    float* fm2   = (float*)sym_addr(g_fm2);
    float* fm3   = (float*)sym_addr(g_fm3);
    float* vp2   = (float*)sym_addr(g_vp2);
    float* fmp2  = (float*)sym_addr(g_fmp2);
    float* fm4   = (float*)sym_addr(g_fm4);
    float* fglob = (float*)sym_addr(g_fglob);
    float* fuse  = (float*)sym_addr(g_fuse);
    float* h1    = (float*)sym_addr(g_h1);
    float* h2    = (float*)sym_addr(g_h2);

    // 1. full-res KNN(32)
    knn_kernel<KNN><<<dim3(NV/128, BSZ), 128>>>(vertices, nullptr, NV, NV, nb1);
    // 2. fm0 = conv_surface
    conv_surface_kernel<<<BSZ*NV, 128>>>(vertices, nb1, dir0, fm0);
    // 3-4. fm1 = relu(conv_layer(fm0; w1,b1,d1; 128))
    gemm128<false,false><<<dim3(256/128, (BSZ*NV)/128), 256>>>(fm0, w1, b1, fbuf, BSZ*NV, 256, 128);
    conv_layer_kernel<128,true><<<BSZ*NV, 128>>>(vertices, NV, nb1, fbuf, d1, fm1);
    // 5-6. pool1
    knn_kernel<4><<<dim3(NP1/128, BSZ), 128>>>(vertices, sidx1, NP1, NV, nbp);
    pool_kernel<<<BSZ*NP1, 128>>>(vertices, fm1, NV, 128, sidx1, nbp, NP1, vp1, fmp1);
    // 7. KNN(32) on pooled level 1
    knn_kernel<KNN><<<dim3(NP1/128, BSZ), 128>>>(vp1, nullptr, NP1, NP1, nb2);
    // 8-9. fm2 = relu(conv_layer(fmp1; w2,b2,d2; 256))
    gemm128<false,false><<<dim3(512/128, (BSZ*NP1)/128), 256>>>(fmp1, w2, b2, fbuf, BSZ*NP1, 512, 128);
    conv_layer_kernel<256,true><<<BSZ*NP1, 256>>>(vp1, NP1, nb2, fbuf, d2, fm2);
    // 10-11. fm3 = relu(conv_layer(fm2; w3,b3,d3; 256))
    gemm128<false,false><<<dim3(512/128, (BSZ*NP1)/128), 256>>>(fm2, w3, b3, fbuf, BSZ*NP1, 512, 256);
    conv_layer_kernel<256,true><<<BSZ*NP1, 256>>>(vp1, NP1, nb2, fbuf, d3, fm3);
    // 12-13. pool2
    knn_kernel<4><<<dim3(NP2/128, BSZ), 128>>>(vp1, sidx2, NP2, NP1, nbp);
    pool_kernel<<<BSZ*NP2, 256>>>(vp1, fm3, NP1, 256, sidx2, nbp, NP2, vp2, fmp2);
    // 14. KNN(32) on pooled level 2
    knn_kernel<KNN><<<dim3(NP2/128, BSZ), 128>>>(vp2, nullptr, NP2, NP2, nb3);
    // 15-16. fm4 = conv_layer(fmp2; w4,b4,d4; 512)  (no relu)
    gemm128<false,false><<<dim3(1024/128, (BSZ*NP2)/128), 256>>>(fmp2, w4, b4, fbuf, BSZ*NP2, 1024, 256);
    conv_layer_kernel<512,false><<<BSZ*NP2, 256>>>(vp2, NP2, nb3, fbuf, d4, fm4);
    // 17. global max feature
    fglobal_kernel<<<BSZ, 512>>>(fm4, fglob);
    // 18. nearest-neighbor upsample indices
    nearest_kernel<<<dim3(NV/128, BSZ), 128>>>(vertices, vp1, NV, NP1, near1);
    nearest_kernel<<<dim3(NV/128, BSZ), 128>>>(vertices, vp2, NV, NP2, near2);
    // 19. fuse (16384 x 1792)
    fuse_kernel<<<BSZ*NV, 256>>>(fm0, fm1, fm2, fm3, fm4, fglob, near1, near2, fuse);
    // 20-22. MLP head
    gemm128<true,true ><<<dim3(512/128, (BSZ*NV)/128), 256>>>(fuse, cw1, cb1, h1, BSZ*NV, 512, 1792);
    gemm128<true,true ><<<dim3(512/128, (BSZ*NV)/128), 256>>>(h1,   cw2, cb2, h2, BSZ*NV, 512, 512);
    head_kernel<<<(BSZ*NV)/16, 256>>>(h2, cw3, cb3, out);
}